// round 6
// baseline (speedup 1.0000x reference)
#include <cuda_runtime.h>
#include <cuda_bf16.h>

// PatchShuffle: T=1024 (16 rows x 64 cols), B=64, C=768, STRIPE_W=48.
// Outputs concatenated as float32:
//   visible       [256*64*768]   gather of shuffled rows 0..255
//   fwd           [1024*64]      forward permutation indices (as float)
//   bwd           [1024*64]      inverse permutation indices (as float)
//   stripe_bounds [2*64]         {start, start+48} per batch
//
// perm(b, j) closed form (stable argsort of col + 64*in_stripe):
//   s = start[b]
//   j <  s        -> j
//   s <= j < 16   -> j + 48
//   j >= 16       -> s + (j-16)
// inverse:
//   col <  s        -> col
//   s <= col < s+48 -> 16 + (col - s)
//   col >= s+48     -> col - 48

#define STRIPE_W   48
#define B_         64
#define C_         768
#define C4_        192                        // 768 floats = 192 float4
#define T_VIS      256
#define T_ALL      1024

#define OFF_FWD    (T_VIS * B_ * C_)          // 12,582,912 floats
#define N_FWD      (T_ALL * B_)               // 65,536
#define OFF_BWD    (OFF_FWD + N_FWD)
#define OFF_SB     (OFF_BWD + N_FWD)

#define THREADS    256
#define WARPS_PB   8                          // warps per block
#define N_PAIRS    (T_VIS * B_)               // 16,384 (t,b) pairs
#define VIS_BLOCKS (N_PAIRS / WARPS_PB)       // 2048 exactly
#define N_TAIL     (2 * N_FWD + 128)          // 131,200
#define TAIL_BLOCKS ((N_TAIL + THREADS - 1) / THREADS)  // 513

__device__ __forceinline__ int perm_of(int s, int j) {
    return (j < s) ? j : ((j < 16) ? (j + STRIPE_W) : (s + (j - 16)));
}

__device__ __forceinline__ int inv_of(int s, int col) {
    return (col < s) ? col : ((col < s + STRIPE_W) ? (16 + (col - s)) : (col - STRIPE_W));
}

__global__ void __launch_bounds__(THREADS)
patchshuffle_kernel(const float4* __restrict__ patches,
                    const int*    __restrict__ start_cols,
                    float*        __restrict__ out) {
    int bid = blockIdx.x;
    int tid = threadIdx.x;

    if (bid < VIS_BLOCKS) {
        // ---- visible gather: one (t,b) pair per warp, 192 float4 per pair ----
        int wid  = tid >> 5;                  // warp in block
        int lane = tid & 31;
        int pair = bid * WARPS_PB + wid;      // t*64 + b   (warp-uniform)
        int b    = pair & 63;
        int t    = pair >> 6;                 // 0..255
        int row  = t >> 6;                    // 0..3
        int j    = t & 63;
        int s    = __ldg(start_cols + b);     // one broadcast load per warp
        int p    = perm_of(s, j);
        int src_t = (row << 6) + p;

        const float4* src = patches + ((src_t * B_ + b) * C4_) + lane;
        float4*       dst = reinterpret_cast<float4*>(out) + (pair * C4_) + lane;

        // 6 independent, fully-coalesced 512B LDG.128s (front-batched: MLP=6)
        float4 v[6];
        #pragma unroll
        for (int k = 0; k < 6; k++)
            v[k] = src[k * 32];
        #pragma unroll
        for (int k = 0; k < 6; k++)
            __stcs(dst + k * 32, v[k]);       // evict-first: keep read set in L2
        return;
    }

    // ---- tail: index outputs, one element per thread ----
    int r = (bid - VIS_BLOCKS) * THREADS + tid;
    if (r < N_FWD) {
        // fwd[t][b]
        int t   = r >> 6;
        int b   = r & 63;
        int row = t >> 6;
        int j   = t & 63;
        int s   = __ldg(start_cols + b);
        out[OFF_FWD + r] = (float)((row << 6) + perm_of(s, j));
        return;
    }
    r -= N_FWD;
    if (r < N_FWD) {
        // bwd[i][b]
        int i   = r >> 6;
        int b   = r & 63;
        int row = i >> 6;
        int col = i & 63;
        int s   = __ldg(start_cols + b);
        out[OFF_BWD + r] = (float)((row << 6) + inv_of(s, col));
        return;
    }
    r -= N_FWD;
    if (r < 128) {
        // stripe_bounds[2][64]
        int b = r & 63;
        int s = __ldg(start_cols + b);
        out[OFF_SB + r] = (float)((r < 64) ? s : (s + STRIPE_W));
    }
}

extern "C" void kernel_launch(void* const* d_in, const int* in_sizes, int n_in,
                              void* d_out, int out_size) {
    const float4* patches    = (const float4*)d_in[0];
    const int*    start_cols = (const int*)d_in[1];
    float*        out        = (float*)d_out;

    patchshuffle_kernel<<<VIS_BLOCKS + TAIL_BLOCKS, THREADS>>>(patches, start_cols, out);
}

// round 8
// speedup vs baseline: 1.0015x; 1.0015x over previous
#include <cuda_runtime.h>
#include <cuda_bf16.h>

// PatchShuffle: T=1024 (16 rows x 64 cols), B=64, C=768, STRIPE_W=48.
// Outputs concatenated as float32:
//   visible       [256*64*768]   gather of shuffled rows 0..255
//   fwd           [1024*64]      forward permutation (as float)
//   bwd           [1024*64]      inverse permutation (as float)
//   stripe_bounds [2*64]         {start, start+48} per batch
//
// perm(b, j):  s = start[b]
//   j <  s        -> j
//   s <= j < 16   -> j + 48
//   j >= 16       -> s + (j-16)
// inverse:
//   col <  s        -> col
//   s <= col < s+48 -> 16 + (col - s)
//   col >= s+48     -> col - 48

#define STRIPE_W   48
#define B_         64
#define C_         768
#define C4_        192
#define T_VIS      256
#define T_ALL      1024

#define N_VIS4     (T_VIS * B_ * C4_)        // 3,145,728 float4
#define OFF_FWD    (T_VIS * B_ * C_)         // 12,582,912 floats
#define N_FWD      (T_ALL * B_)              // 65,536
#define OFF_BWD    (OFF_FWD + N_FWD)
#define OFF_SB     (OFF_BWD + N_FWD)

#define ILP        8
#define THREADS    256
#define VIS_STRIDE (N_VIS4 / ILP)            // 393,216 = 2048*192 (mult of 192 and 64)
#define VIS_BLOCKS (VIS_STRIDE / THREADS)    // 1536 exactly
#define PAIR_STEP  (VIS_STRIDE / C4_)        // 2048 pairs per ILP step
#define SRC_STEP   (64 * B_ * C4_)           // 786,432 float4 per row step (t += 64)

#define N_TAIL     (2 * N_FWD + 128)
#define TAIL_BLOCKS ((N_TAIL + THREADS - 1) / THREADS)  // 513

__device__ __forceinline__ int perm_of(int s, int j) {
    return (j < s) ? j : ((j < 16) ? (j + STRIPE_W) : (s + (j - 16)));
}

__device__ __forceinline__ int inv_of(int s, int col) {
    return (col < s) ? col : ((col < s + STRIPE_W) ? (16 + (col - s)) : (col - STRIPE_W));
}

__global__ void __launch_bounds__(THREADS)
patchshuffle_kernel(const float4* __restrict__ patches,
                    const int*    __restrict__ start_cols,
                    float*        __restrict__ out) {
    int bid = blockIdx.x;
    int tid = threadIdx.x;

    if (bid < VIS_BLOCKS) {
        // ---- visible gather: flat layout, 8 items/thread at stride 393,216 ----
        // base in [0, 393216): pair0 in [0, 2048) -> t0 in [0,32), row0 = 0.
        int base  = bid * THREADS + tid;
        int c4    = base % C4_;               // invariant across all 8 items
        int pair0 = base / C4_;
        int b     = pair0 & 63;               // invariant
        int t0    = pair0 >> 6;               // in [0,32); j alternates t0 / t0+32
        int s     = __ldg(start_cols + b);    // ONE scoreboarded load per thread

        int p_even = perm_of(s, t0);          // j = t0 (< 32)
        int p_odd  = s + t0 + 16;             // j = t0+32 >= 32 -> always stripe branch

        // float4 base addresses for the two j-parities (row 0)
        int src_even = (p_even * B_ + b) * C4_ + c4;
        int src_odd  = (p_odd  * B_ + b) * C4_ + c4;

        float4 v[ILP];
        #pragma unroll
        for (int m = 0; m < ILP; m++) {
            int src = ((m & 1) ? src_odd : src_even) + (m >> 1) * SRC_STEP;
            v[m] = patches[src];              // 8 independent LDG.128, const offsets
        }
        float4* o4 = reinterpret_cast<float4*>(out);
        #pragma unroll
        for (int m = 0; m < ILP; m++)
            __stcs(o4 + base + m * VIS_STRIDE, v[m]);
        return;
    }

    // ---- tail: index outputs ----
    int r = (bid - VIS_BLOCKS) * THREADS + tid;
    if (r < N_FWD) {
        int t   = r >> 6;
        int b   = r & 63;
        int row = t >> 6;
        int j   = t & 63;
        int s   = __ldg(start_cols + b);
        out[OFF_FWD + r] = (float)((row << 6) + perm_of(s, j));
        return;
    }
    r -= N_FWD;
    if (r < N_FWD) {
        int i   = r >> 6;
        int b   = r & 63;
        int row = i >> 6;
        int col = i & 63;
        int s   = __ldg(start_cols + b);
        out[OFF_BWD + r] = (float)((row << 6) + inv_of(s, col));
        return;
    }
    r -= N_FWD;
    if (r < 128) {
        int b = r & 63;
        int s = __ldg(start_cols + b);
        out[OFF_SB + r] = (float)((r < 64) ? s : (s + STRIPE_W));
    }
}

extern "C" void kernel_launch(void* const* d_in, const int* in_sizes, int n_in,
                              void* d_out, int out_size) {
    const float4* patches    = (const float4*)d_in[0];
    const int*    start_cols = (const int*)d_in[1];
    float*        out        = (float*)d_out;

    patchshuffle_kernel<<<VIS_BLOCKS + TAIL_BLOCKS, THREADS>>>(patches, start_cols, out);
}

// round 9
// speedup vs baseline: 1.4363x; 1.4341x over previous
#include <cuda_runtime.h>
#include <cuda_bf16.h>

// PatchShuffle: T=1024 (16 rows x 64 cols), B=64, C=768, STRIPE_W=48.
// Outputs concatenated as float32:
//   visible       [256*64*768]   gather of shuffled rows 0..255
//   fwd           [1024*64]      forward permutation (as float)
//   bwd           [1024*64]      inverse permutation (as float)
//   stripe_bounds [2*64]         {start, start+48} per batch
//
// perm(b, j):  s = start[b]
//   j <  s        -> j
//   s <= j < 16   -> j + 48
//   j >= 16       -> s + (j-16)
// inverse:
//   col <  s        -> col
//   s <= col < s+48 -> 16 + (col - s)
//   col >= s+48     -> col - 48
//
// NOTE: the visible-gather loop reproduces Round-3's exact issue pattern
// (per-item idx math + __ldg in the address chain). That staggering avoids
// the front-batched-LDG cross-CTA L1tex queue contention that regressed
// R5/R6 to 21us. Do not "optimize" the address math into batched form.

#define STRIPE_W   48
#define B_         64
#define C_         768
#define C4_        192
#define T_VIS      256
#define T_ALL      1024

#define N_VIS4     (T_VIS * B_ * C4_)        // 3,145,728 float4 items
#define OFF_FWD    (T_VIS * B_ * C_)         // 12,582,912 floats
#define N_FWD      (T_ALL * B_)              // 65,536
#define OFF_BWD    (OFF_FWD + N_FWD)
#define OFF_SB     (OFF_BWD + N_FWD)

#define ILP        4
#define THREADS    256
#define VIS_BLOCKS (N_VIS4 / (THREADS * ILP))    // 3072 exactly
#define VIS_STRIDE (VIS_BLOCKS * THREADS)        // 786,432
#define N_TAIL     (2 * N_FWD + 128)             // 131,200
#define TAIL_BLOCKS ((N_TAIL + THREADS - 1) / THREADS)  // 513 (folded into grid)

__device__ __forceinline__ int perm_of(int s, int j) {
    return (j < s) ? j : ((j < 16) ? (j + STRIPE_W) : (s + (j - 16)));
}

__device__ __forceinline__ int inv_of(int s, int col) {
    return (col < s) ? col : ((col < s + STRIPE_W) ? (16 + (col - s)) : (col - STRIPE_W));
}

__global__ void __launch_bounds__(THREADS)
patchshuffle_kernel(const float4* __restrict__ patches,
                    const int*    __restrict__ start_cols,
                    float*        __restrict__ out) {
    int bid = blockIdx.x;
    int tid = threadIdx.x;

    // ---- visible gather: R3's exact pattern (4 staggered float4 per thread) ----
    {
        int base = bid * THREADS + tid;
        float4 v[ILP];
        #pragma unroll
        for (int k = 0; k < ILP; k++) {
            int idx  = base + k * VIS_STRIDE;   // always < N_VIS4 (exact fit)
            int c4   = idx % C4_;
            int pair = idx / C4_;               // t*64 + b
            int b    = pair & 63;
            int t    = pair >> 6;               // 0..255
            int row  = t >> 6;                  // 0..3
            int j    = t & 63;
            int s    = __ldg(start_cols + b);
            int p    = perm_of(s, j);
            v[k] = patches[(((row << 6) + p) * B_ + b) * C4_ + c4];
        }
        float4* o4 = reinterpret_cast<float4*>(out);
        #pragma unroll
        for (int k = 0; k < ILP; k++)
            o4[base + k * VIS_STRIDE] = v[k];   // default policy: keep in L2
    }

    // ---- tail folded into the first 513 blocks (no straggler wave) ----
    if (bid < TAIL_BLOCKS) {
        int r = bid * THREADS + tid;
        if (r < N_FWD) {
            // fwd[t][b]
            int t   = r >> 6;
            int b   = r & 63;
            int row = t >> 6;
            int j   = t & 63;
            int s   = __ldg(start_cols + b);
            out[OFF_FWD + r] = (float)((row << 6) + perm_of(s, j));
            return;
        }
        r -= N_FWD;
        if (r < N_FWD) {
            // bwd[i][b]
            int i   = r >> 6;
            int b   = r & 63;
            int row = i >> 6;
            int col = i & 63;
            int s   = __ldg(start_cols + b);
            out[OFF_BWD + r] = (float)((row << 6) + inv_of(s, col));
            return;
        }
        r -= N_FWD;
        if (r < 128) {
            // stripe_bounds[2][64]
            int b = r & 63;
            int s = __ldg(start_cols + b);
            out[OFF_SB + r] = (float)((r < 64) ? s : (s + STRIPE_W));
        }
    }
}

extern "C" void kernel_launch(void* const* d_in, const int* in_sizes, int n_in,
                              void* d_out, int out_size) {
    const float4* patches    = (const float4*)d_in[0];
    const int*    start_cols = (const int*)d_in[1];
    float*        out        = (float*)d_out;

    patchshuffle_kernel<<<VIS_BLOCKS, THREADS>>>(patches, start_cols, out);
}